// round 2
// baseline (speedup 1.0000x reference)
#include <cuda_runtime.h>
#include <cuda_fp16.h>
#include <cstdint>

// out[b,o] = sum_i tanh(x[b,i]*t) * W[o,i],  W = sum_p coef[o,i,p]
// B=131072, I=O=128. fp32 in/out.
//
// sm_103 (non-'a') target: tcgen05 unavailable -> mma.sync.m16n8k16 (HMMA).
// Split precision on W: out = vh @ Wh + vh @ Wl (fp16 inputs, fp32 accum).
// Expected rel_err ~2e-4.

static constexpr int IDIM = 128;
static constexpr int ODIM = 128;
static constexpr int TILE_M = 128;

// B fragments in mma register layout: [pass(2)][nt(16)][kt(8)][lane(32)][reg(2)]
// each entry one .f16x2 word. 64KB total, stays hot in L2.
__device__ uint32_t g_BF[2 * 16 * 8 * 32 * 2];

// ---------------------------------------------------------------------------
// prep: W[o,i] = sum_p coef[o,i,p]; split into fp16 hi/lo; write B fragments.
// 8192 threads, each handles (nt,kt,lane,reg) -> two (n,k) columns.
// ---------------------------------------------------------------------------
__global__ void prep_w_kernel(const float* __restrict__ coef) {
    int idx = blockIdx.x * blockDim.x + threadIdx.x;   // 0..8191
    int nt = idx >> 9;
    int kt = (idx >> 6) & 7;
    int lane = (idx >> 1) & 31;
    int reg = idx & 1;
    int n = nt * 8 + (lane >> 2);
    int k = kt * 16 + (lane & 3) * 2 + reg * 8;

    const float4* c0 = reinterpret_cast<const float4*>(coef + ((size_t)n * 128 + k) * 16);
    const float4* c1 = reinterpret_cast<const float4*>(coef + ((size_t)n * 128 + k + 1) * 16);
    float s0 = 0.f, s1 = 0.f;
#pragma unroll
    for (int j = 0; j < 4; j++) {
        float4 a = c0[j];
        s0 += (a.x + a.y) + (a.z + a.w);
    }
#pragma unroll
    for (int j = 0; j < 4; j++) {
        float4 a = c1[j];
        s1 += (a.x + a.y) + (a.z + a.w);
    }
    __half h0 = __float2half_rn(s0);
    __half h1 = __float2half_rn(s1);
    __half l0 = __float2half_rn(s0 - __half2float(h0));
    __half l1 = __float2half_rn(s1 - __half2float(h1));
    __half2 hh = __halves2half2(h0, h1);   // low = k, high = k+1
    __half2 ll = __halves2half2(l0, l1);
    int base = ((nt * 8 + kt) * 32 + lane) * 2 + reg;
    g_BF[base] = *reinterpret_cast<uint32_t*>(&hh);
    g_BF[16 * 8 * 32 * 2 + base] = *reinterpret_cast<uint32_t*>(&ll);
}

// ---------------------------------------------------------------------------
// accurate-enough tanh built on MUFU.EX2 (rel err ~1e-7), fast-math-proof
// ---------------------------------------------------------------------------
__device__ __forceinline__ float tanh_acc(float v) {
    v = fminf(fmaxf(v, -10.f), 10.f);
    float e = __expf(2.f * v);          // EX2-based, no overflow after clamp
    return __fdividef(e - 1.f, e + 1.f);
}

__device__ __forceinline__ uint32_t pack_h2(float a, float b) {
    __half2 h = __floats2half2_rn(a, b);   // low = a, high = b
    return *reinterpret_cast<uint32_t*>(&h);
}

#define MMA16816(d0, d1, d2, d3, A, b0, b1)                                   \
    asm volatile(                                                             \
        "mma.sync.aligned.m16n8k16.row.col.f32.f16.f16.f32 "                  \
        "{%0,%1,%2,%3}, {%4,%5,%6,%7}, {%8,%9}, {%0,%1,%2,%3};"               \
        : "+f"(d0), "+f"(d1), "+f"(d2), "+f"(d3)                              \
        : "r"((A).x), "r"((A).y), "r"((A).z), "r"((A).w), "r"(b0), "r"(b1))

// SMEM layout: [0, 64KB) B fragments (both passes); [64KB, 96KB) A fragments.
static constexpr int SMEM_BF = 0;
static constexpr int SMEM_AF = 65536;
static constexpr int SMEM_TOTAL = 65536 + 32768;   // 96 KB

// ---------------------------------------------------------------------------
// main: CTA = 128 rows. 8 warps = 2 mgroups x 4 ngroups; warp = 64r x 32c.
// Stage 1: tanh + fp16 A fragments -> SMEM (each x element exactly once).
// Stage 2: 256 HMMA per warp, fp32 accum, direct float2 stores.
// ---------------------------------------------------------------------------
__global__ __launch_bounds__(256, 2) void fused_tanh_gemm_kernel(
    const float* __restrict__ x, const float* __restrict__ tanh_range,
    float* __restrict__ out)
{
    extern __shared__ __align__(16) char smem[];
    const int tid = threadIdx.x;
    const int lane = tid & 31;
    const int wid = tid >> 5;
    const size_t rowBase = (size_t)blockIdx.x * TILE_M;

    // ---- copy B fragments (L2-hot) into SMEM: 4096 x uint4 ----
    {
        const uint4* src = reinterpret_cast<const uint4*>(g_BF);
        uint4* dst = reinterpret_cast<uint4*>(smem + SMEM_BF);
#pragma unroll
        for (int i = tid; i < 4096; i += 256) dst[i] = src[i];
    }

    // ---- stage 1: A fragments. quad q = (mt, kt, lane) ----
    {
        const float t = __ldg(tanh_range);
        const float* xb = x + rowBase * IDIM;
#pragma unroll
        for (int i = 0; i < 8; i++) {
            int q = tid + i * 256;
            int mt = q >> 8;
            int kt = (q >> 5) & 7;
            int l = q & 31;
            int r = mt * 16 + (l >> 2);
            int c = kt * 16 + (l & 3) * 2;
            float2 v00 = *reinterpret_cast<const float2*>(xb + (size_t)r * 128 + c);
            float2 v10 = *reinterpret_cast<const float2*>(xb + (size_t)(r + 8) * 128 + c);
            float2 v01 = *reinterpret_cast<const float2*>(xb + (size_t)r * 128 + c + 8);
            float2 v11 = *reinterpret_cast<const float2*>(xb + (size_t)(r + 8) * 128 + c + 8);
            uint4 quad;
            quad.x = pack_h2(tanh_acc(v00.x * t), tanh_acc(v00.y * t));  // a0: (r,   c)
            quad.y = pack_h2(tanh_acc(v10.x * t), tanh_acc(v10.y * t));  // a1: (r+8, c)
            quad.z = pack_h2(tanh_acc(v01.x * t), tanh_acc(v01.y * t));  // a2: (r,   c+8)
            quad.w = pack_h2(tanh_acc(v11.x * t), tanh_acc(v11.y * t));  // a3: (r+8, c+8)
            *reinterpret_cast<uint4*>(smem + SMEM_AF + (((mt * 8 + kt) * 32 + l) << 4)) = quad;
        }
    }
    __syncthreads();

    // ---- stage 2 ----
    const int mgroup = wid >> 2;   // 0..1  -> rows mgroup*64
    const int ngroup = wid & 3;    // 0..3  -> cols ngroup*32
    float acc[4][4][4];
#pragma unroll
    for (int a = 0; a < 4; a++)
#pragma unroll
        for (int b = 0; b < 4; b++)
#pragma unroll
            for (int cc = 0; cc < 4; cc++) acc[a][b][cc] = 0.f;

#pragma unroll
    for (int kt = 0; kt < 8; kt++) {
        uint4 af[4];
#pragma unroll
        for (int mt = 0; mt < 4; mt++) {
            int mtg = mgroup * 4 + mt;
            af[mt] = *reinterpret_cast<const uint4*>(
                smem + SMEM_AF + (((mtg * 8 + kt) * 32 + lane) << 4));
        }
        uint2 bh[4], bl[4];
#pragma unroll
        for (int nt = 0; nt < 4; nt++) {
            int ntg = ngroup * 4 + nt;
            int off = ((ntg * 8 + kt) * 32 + lane) << 3;
            bh[nt] = *reinterpret_cast<const uint2*>(smem + SMEM_BF + off);
            bl[nt] = *reinterpret_cast<const uint2*>(smem + SMEM_BF + 32768 + off);
        }
#pragma unroll
        for (int mt = 0; mt < 4; mt++) {
#pragma unroll
            for (int nt = 0; nt < 4; nt++) {
                MMA16816(acc[mt][nt][0], acc[mt][nt][1], acc[mt][nt][2], acc[mt][nt][3],
                         af[mt], bh[nt].x, bh[nt].y);
                MMA16816(acc[mt][nt][0], acc[mt][nt][1], acc[mt][nt][2], acc[mt][nt][3],
                         af[mt], bl[nt].x, bl[nt].y);
            }
        }
    }

    // ---- epilogue: d0,d1 -> (r, c..c+1); d2,d3 -> (r+8, c..c+1) ----
#pragma unroll
    for (int mt = 0; mt < 4; mt++) {
        int r0 = mgroup * 64 + mt * 16 + (lane >> 2);
#pragma unroll
        for (int nt = 0; nt < 4; nt++) {
            int c0 = ngroup * 32 + nt * 8 + (lane & 3) * 2;
            float* o = out + (rowBase + r0) * ODIM + c0;
            *reinterpret_cast<float2*>(o) = make_float2(acc[mt][nt][0], acc[mt][nt][1]);
            *reinterpret_cast<float2*>(o + 8 * ODIM) = make_float2(acc[mt][nt][2], acc[mt][nt][3]);
        }
    }
}

// ---------------------------------------------------------------------------
extern "C" void kernel_launch(void* const* d_in, const int* in_sizes, int n_in,
                              void* d_out, int out_size) {
    const float* x = (const float*)d_in[0];
    const float* coef = (const float*)d_in[1];
    const float* tr = (const float*)d_in[2];
    float* out = (float*)d_out;

    cudaFuncSetAttribute(fused_tanh_gemm_kernel,
                         cudaFuncAttributeMaxDynamicSharedMemorySize, SMEM_TOTAL);

    prep_w_kernel<<<32, 256>>>(coef);

    int rows = in_sizes[0] / IDIM;     // 131072
    int grid = rows / TILE_M;          // 1024
    fused_tanh_gemm_kernel<<<grid, 256, SMEM_TOTAL>>>(x, tr, out);
}

// round 3
// speedup vs baseline: 1.3359x; 1.3359x over previous
#include <cuda_runtime.h>
#include <cuda_fp16.h>
#include <cstdint>

// out[b,o] = sum_i tanh(x[b,i]*t) * W[o,i],  W = sum_p coef[o,i,p]
// B=131072, I=O=128. fp32 in/out.
//
// mma.sync.m16n8k16 fp16 (fp32 accum), single-pass fp16 W (rel_err ~2.6e-4).
// TILE_M=64, 8 warps, 32x32 warp tiles, 48KB smem, 4 CTAs/SM (50% occ).

static constexpr int IDIM = 128;
static constexpr int ODIM = 128;
static constexpr int TILE_M = 64;

// B fragments in mma register layout: [nt(16)][kt(8)][lane(32)][reg(2)]
// one .f16x2 word each -> 32KB, stays hot in L2.
__device__ uint32_t g_BF[16 * 8 * 32 * 2];

// ---------------------------------------------------------------------------
// prep: W[o,i] = sum_p coef[o,i,p] -> fp16 -> B fragments.
// ---------------------------------------------------------------------------
__global__ void prep_w_kernel(const float* __restrict__ coef) {
    int idx = blockIdx.x * blockDim.x + threadIdx.x;   // 0..8191
    int nt = idx >> 9;
    int kt = (idx >> 6) & 7;
    int lane = (idx >> 1) & 31;
    int reg = idx & 1;
    int n = nt * 8 + (lane >> 2);
    int k = kt * 16 + (lane & 3) * 2 + reg * 8;

    const float4* c0 = reinterpret_cast<const float4*>(coef + ((size_t)n * 128 + k) * 16);
    const float4* c1 = reinterpret_cast<const float4*>(coef + ((size_t)n * 128 + k + 1) * 16);
    float s0 = 0.f, s1 = 0.f;
#pragma unroll
    for (int j = 0; j < 4; j++) {
        float4 a = c0[j];
        s0 += (a.x + a.y) + (a.z + a.w);
    }
#pragma unroll
    for (int j = 0; j < 4; j++) {
        float4 a = c1[j];
        s1 += (a.x + a.y) + (a.z + a.w);
    }
    __half2 hh = __floats2half2_rn(s0, s1);   // low = k, high = k+1
    g_BF[((nt * 8 + kt) * 32 + lane) * 2 + reg] = *reinterpret_cast<uint32_t*>(&hh);
}

// ---------------------------------------------------------------------------
// accurate tanh via MUFU.EX2 + MUFU.RCP (rel err ~1e-7), fast-math-proof
// ---------------------------------------------------------------------------
__device__ __forceinline__ float tanh_acc(float v) {
    v = fminf(fmaxf(v, -10.f), 10.f);
    float e = __expf(2.f * v);
    return __fdividef(e - 1.f, e + 1.f);
}

__device__ __forceinline__ uint32_t pack_h2(float a, float b) {
    __half2 h = __floats2half2_rn(a, b);   // low = a, high = b
    return *reinterpret_cast<uint32_t*>(&h);
}

#define MMA16816(d0, d1, d2, d3, A, b0, b1)                                   \
    asm volatile(                                                             \
        "mma.sync.aligned.m16n8k16.row.col.f32.f16.f16.f32 "                  \
        "{%0,%1,%2,%3}, {%4,%5,%6,%7}, {%8,%9}, {%0,%1,%2,%3};"               \
        : "+f"(d0), "+f"(d1), "+f"(d2), "+f"(d3)                              \
        : "r"((A).x), "r"((A).y), "r"((A).z), "r"((A).w), "r"(b0), "r"(b1))

// SMEM: [0, 32KB) B fragments; [32KB, 48KB) A fragments (64 rows).
static constexpr int SMEM_BF = 0;
static constexpr int SMEM_AF = 32768;
static constexpr int SMEM_TOTAL = 32768 + 16384;   // 48 KB

// ---------------------------------------------------------------------------
// main: CTA = 64 rows. 8 warps = 2 mgroups x 4 ngroups; warp = 32r x 32c.
// ---------------------------------------------------------------------------
__global__ __launch_bounds__(256, 4) void fused_tanh_gemm_kernel(
    const float* __restrict__ x, const float* __restrict__ tanh_range,
    float* __restrict__ out)
{
    extern __shared__ __align__(16) char smem[];
    const int tid = threadIdx.x;
    const int lane = tid & 31;
    const int wid = tid >> 5;
    const size_t rowBase = (size_t)blockIdx.x * TILE_M;

    // ---- copy B fragments (L2-hot) into SMEM: 2048 x uint4 ----
    {
        const uint4* src = reinterpret_cast<const uint4*>(g_BF);
        uint4* dst = reinterpret_cast<uint4*>(smem + SMEM_BF);
#pragma unroll
        for (int i = tid; i < 2048; i += 256) dst[i] = src[i];
    }

    // ---- stage 1: A fragments. 1024 quads = 4 mt x 8 kt x 32 lanes ----
    {
        const float t = __ldg(tanh_range);
        const float* xb = x + rowBase * IDIM;
#pragma unroll
        for (int i = 0; i < 4; i++) {
            int q = tid + i * 256;
            int mt = q >> 8;
            int kt = (q >> 5) & 7;
            int l = q & 31;
            int r = mt * 16 + (l >> 2);
            int c = kt * 16 + (l & 3) * 2;
            float2 v00 = *reinterpret_cast<const float2*>(xb + (size_t)r * 128 + c);
            float2 v10 = *reinterpret_cast<const float2*>(xb + (size_t)(r + 8) * 128 + c);
            float2 v01 = *reinterpret_cast<const float2*>(xb + (size_t)r * 128 + c + 8);
            float2 v11 = *reinterpret_cast<const float2*>(xb + (size_t)(r + 8) * 128 + c + 8);
            uint4 quad;
            quad.x = pack_h2(tanh_acc(v00.x * t), tanh_acc(v00.y * t));  // (r,   c)
            quad.y = pack_h2(tanh_acc(v10.x * t), tanh_acc(v10.y * t));  // (r+8, c)
            quad.z = pack_h2(tanh_acc(v01.x * t), tanh_acc(v01.y * t));  // (r,   c+8)
            quad.w = pack_h2(tanh_acc(v11.x * t), tanh_acc(v11.y * t));  // (r+8, c+8)
            *reinterpret_cast<uint4*>(smem + SMEM_AF + (((mt * 8 + kt) * 32 + l) << 4)) = quad;
        }
    }
    __syncthreads();

    // ---- stage 2: warp tile 32(M) x 32(N); 64 HMMA ----
    const int mgroup = wid >> 2;   // 0..1 -> rows mgroup*32
    const int ngroup = wid & 3;    // 0..3 -> cols ngroup*32
    float acc[2][4][4];
#pragma unroll
    for (int a = 0; a < 2; a++)
#pragma unroll
        for (int b = 0; b < 4; b++)
#pragma unroll
            for (int cc = 0; cc < 4; cc++) acc[a][b][cc] = 0.f;

#pragma unroll 2
    for (int kt = 0; kt < 8; kt++) {
        uint4 af[2];
#pragma unroll
        for (int mt = 0; mt < 2; mt++) {
            int mtg = mgroup * 2 + mt;
            af[mt] = *reinterpret_cast<const uint4*>(
                smem + SMEM_AF + (((mtg * 8 + kt) * 32 + lane) << 4));
        }
        uint2 bh[4];
#pragma unroll
        for (int nt = 0; nt < 4; nt++) {
            int ntg = ngroup * 4 + nt;
            bh[nt] = *reinterpret_cast<const uint2*>(
                smem + SMEM_BF + (((ntg * 8 + kt) * 32 + lane) << 3));
        }
#pragma unroll
        for (int mt = 0; mt < 2; mt++) {
#pragma unroll
            for (int nt = 0; nt < 4; nt++) {
                MMA16816(acc[mt][nt][0], acc[mt][nt][1], acc[mt][nt][2], acc[mt][nt][3],
                         af[mt], bh[nt].x, bh[nt].y);
            }
        }
    }

    // ---- epilogue: d0,d1 -> (r, c..c+1); d2,d3 -> (r+8, c..c+1) ----
#pragma unroll
    for (int mt = 0; mt < 2; mt++) {
        int r0 = mgroup * 32 + mt * 16 + (lane >> 2);
#pragma unroll
        for (int nt = 0; nt < 4; nt++) {
            int c0 = ngroup * 32 + nt * 8 + (lane & 3) * 2;
            float* o = out + (rowBase + r0) * ODIM + c0;
            *reinterpret_cast<float2*>(o) = make_float2(acc[mt][nt][0], acc[mt][nt][1]);
            *reinterpret_cast<float2*>(o + 8 * ODIM) = make_float2(acc[mt][nt][2], acc[mt][nt][3]);
        }
    }
}

// ---------------------------------------------------------------------------
extern "C" void kernel_launch(void* const* d_in, const int* in_sizes, int n_in,
                              void* d_out, int out_size) {
    const float* x = (const float*)d_in[0];
    const float* coef = (const float*)d_in[1];
    const float* tr = (const float*)d_in[2];
    float* out = (float*)d_out;

    cudaFuncSetAttribute(fused_tanh_gemm_kernel,
                         cudaFuncAttributeMaxDynamicSharedMemorySize, SMEM_TOTAL);

    prep_w_kernel<<<32, 256>>>(coef);

    int rows = in_sizes[0] / IDIM;     // 131072
    int grid = rows / TILE_M;          // 2048
    fused_tanh_gemm_kernel<<<grid, 256, SMEM_TOTAL>>>(x, tr, out);
}